// round 1
// baseline (speedup 1.0000x reference)
#include <cuda_runtime.h>
#include <cuda_bf16.h>

#define LMAX 32
#define NCMAX 400

// scratch: per-(m,p) partial |0.1^|e00/rng| - 1| values (M*P = 6400 max)
__device__ float g_scratch[64 * 100];

__device__ __forceinline__ float f_rcp(float x) {
    float r; asm("rcp.approx.f32 %0, %1;" : "=f"(r) : "f"(x)); return r;
}
__device__ __forceinline__ float f_sqrt(float x) {
    float r; asm("sqrt.approx.f32 %0, %1;" : "=f"(r) : "f"(x)); return r;
}

__global__ void __launch_bounds__(128)
disp_kernel(const float* __restrict__ vlist, const float* __restrict__ tlist,
            const float* __restrict__ dly, const float* __restrict__ bly,
            const float* __restrict__ Clist,
            int M, int L, int P, int NC)
{
    __shared__ float s_xka[LMAX], s_xkb[LMAX], s_gammk[LMAX], s_d[LMAX];
    __shared__ float s_rho[LMAX], s_irho[LMAX];
    __shared__ float s_C[NCMAX];
    __shared__ float s_wmax[4], s_wmin[4], s_e00;

    const int mp  = blockIdx.x;          // mp = m*P + p
    const int m   = mp / P;
    const int tid = threadIdx.x;

    const float omega = fmaxf(6.28318530717958647692f / tlist[mp], 1.0e-4f);
    const float v     = vlist[mp];
    const float io    = f_rcp(omega);

    // Phase 0: per-(m,p,layer) constants, shared across all 401 wvno points
    for (int l = tid; l < L; l += blockDim.x) {
        float bb = bly[m * L + l];
        float dd = dly[m * L + l];
        float b2 = bb * bb;
        float aa = 0.9409f + 2.0947f * bb - 0.8206f * b2 + 0.2683f * b2 * bb
                 - 0.0251f * b2 * b2;
        float a2 = aa * aa;
        float rho = 1.6612f * aa - 0.4721f * a2 + 0.0671f * a2 * aa
                  - 0.0043f * a2 * a2 + 0.000106f * a2 * a2 * aa;
        s_xka[l]   = __fdividef(omega, aa);
        s_xkb[l]   = __fdividef(omega, bb);
        float tt   = bb * io;
        s_gammk[l] = 2.0f * tt * tt;
        s_d[l]     = dd;
        s_rho[l]   = rho;
        s_irho[l]  = f_rcp(rho);
    }
    for (int i = tid; i < NC; i += blockDim.x) s_C[i] = Clist[i];
    __syncthreads();

    float lmax = -3.4e38f, lmin = 3.4e38f;

    // Phase 1: 400 C-grid points + 1 actual-wvno point (item i == NC)
    for (int i = tid; i <= NC; i += blockDim.x) {
        const float wv    = (i < NC) ? __fdividef(omega, s_C[i]) : __fdividef(omega, v);
        const float wvno2 = wv * wv;
        const float wvno4 = wvno2 * wvno2;
        const float tneg  = -2.0f * wvno2;

        // ---- halfspace initial vector (layer L-1) ----
        float e0, e1, e2, e3, e4;
        {
            const int lh = L - 1;
            float xka = s_xka[lh], xkb = s_xkb[lh], gk = s_gammk[lh], r = s_rho[lh];
            float ra = f_sqrt(fabsf(wvno2 - xka * xka));
            float rb = f_sqrt(fabsf(wvno2 - xkb * xkb));
            float gam = gk * wvno2, gamm1 = gam - 1.0f, rarb = ra * rb;
            e0 = r * r * (gamm1 * gamm1 - gam * gk * rarb);
            e1 = -r * ra;
            e2 = r * (gamm1 - gk * rarb);
            e3 = r * rb;
            e4 = wvno2 - rarb;
        }

        // ---- layer recursion L-2 .. 0 ----
        #pragma unroll 1
        for (int l = L - 2; l >= 0; --l) {
            const float xka = s_xka[l], xkb = s_xkb[l];
            const float gk  = s_gammk[l], dm = s_d[l];
            const float rho = s_rho[l],  irho = s_irho[l];
            const float rho2 = rho * rho, irho2 = irho * irho;

            float ra = f_sqrt(fabsf(wvno2 - xka * xka));
            float rb = f_sqrt(fabsf(wvno2 - xkb * xkb));
            float gam = gk * wvno2;
            float pp = ra * dm, qq = rb * dm;

            float cosp, w, x, pex;
            if (wv < xka) {
                float sp, cp; __sincosf(pp, &sp, &cp);
                float ras = (ra > 0.0f) ? ra : 1.0f;
                cosp = cp; w = __fdividef(sp, ras); x = -ra * sp; pex = 0.0f;
            } else if (wv > xka) {
                float fac = (pp < 16.0f) ? __expf(-2.0f * pp) : 0.0f;
                cosp = (1.0f + fac) * 0.5f;
                float se = (1.0f - fac) * 0.5f;
                float ras = (ra > 0.0f) ? ra : 1.0f;
                w = __fdividef(se, ras); x = ra * se; pex = pp;
            } else {
                cosp = 1.0f; w = dm; x = 0.0f; pex = 0.0f;
            }

            float cosq, y, z, sex;
            if (wv < xkb) {
                float sq, cq; __sincosf(qq, &sq, &cq);
                float rbs = (rb > 0.0f) ? rb : 1.0f;
                cosq = cq; y = __fdividef(sq, rbs); z = -rb * sq; sex = 0.0f;
            } else if (wv > xkb) {
                float fac = (qq < 16.0f) ? __expf(-2.0f * qq) : 0.0f;
                cosq = (1.0f + fac) * 0.5f;
                float se = (1.0f - fac) * 0.5f;
                float rbs = (rb > 0.0f) ? rb : 1.0f;
                y = __fdividef(se, rbs); z = rb * se; sex = qq;
            } else {
                cosq = 1.0f; y = dm; z = 0.0f; sex = 0.0f;
            }

            float exa = pex + sex;
            float a0 = (exa < 60.0f) ? __expf(-exa) : 0.0f;

            float cpcq = cosp * cosq, cpy = cosp * y, cpz = cosp * z;
            float cqw = cosq * w,     cqx = cosq * x;
            float xy = x * y, xz = x * z, wy = w * y, wz = w * z;

            float gamm1 = gam - 1.0f;
            float twgm1 = gam + gamm1;
            float gmgmk = gam * gk, gmgm1 = gam * gamm1, gm1sq = gamm1 * gamm1;
            float a0pq = a0 - cpcq;

            float c00 = cpcq - 2.0f * gmgm1 * a0pq - gmgmk * xz - wvno2 * gm1sq * wy;
            float c01 = (wvno2 * cpy - cqx) * irho;
            float c02 = -(twgm1 * a0pq + gk * xz + wvno2 * gamm1 * wy) * irho;
            float c03 = (cpz - wvno2 * cqw) * irho;
            float c04 = -(2.0f * wvno2 * a0pq + xz + wvno4 * wy) * irho2;
            float c10 = (gmgmk * cpz - gm1sq * cqw) * rho;
            float c11 = cpcq;
            float c12 = gk * cpz - gamm1 * cqw;
            float c13 = -wz;
            float c30 = (gm1sq * cpy - gmgmk * cqx) * rho;
            float c31 = -xy;
            float c32 = gamm1 * cpy - gk * cqx;
            float c40 = -(2.0f * gmgmk * gm1sq * a0pq + gmgmk * gmgmk * xz
                          + gm1sq * gm1sq * wy) * rho2;
            float c42 = -(gk * gamm1 * twgm1 * a0pq + gam * gk * gk * xz
                          + gamm1 * gm1sq * wy) * rho;
            float c20 = tneg * c42, c21 = tneg * c32;
            float c23 = tneg * c12, c24 = tneg * c02;
            float c22 = a0 + 2.0f * (cpcq - c00);

            float n0 = e0 * c00 + e1 * c10 + e2 * c20 + e3 * c30 + e4 * c40;
            float n1 = e0 * c01 + e1 * c11 + e2 * c21 + e3 * c31 + e4 * c30;
            float n2 = e0 * c02 + e1 * c12 + e2 * c22 + e3 * c32 + e4 * c42;
            float n3 = e0 * c03 + e1 * c13 + e2 * c23 + e3 * c11 + e4 * c10;
            float n4 = e0 * c04 + e1 * c03 + e2 * c24 + e3 * c01 + e4 * c00;

            float t1 = fmaxf(fmaxf(fmaxf(fabsf(n0), fabsf(n1)),
                                   fmaxf(fabsf(n2), fabsf(n3))), fabsf(n4));
            t1 = (t1 < 1e-30f) ? 1.0f : t1;
            float it1 = f_rcp(t1);
            e0 = n0 * it1; e1 = n1 * it1; e2 = n2 * it1;
            e3 = n3 * it1; e4 = n4 * it1;
        }

        if (i < NC) {
            lmax = fmaxf(lmax, e0);
            lmin = fminf(lmin, e0);
        } else {
            s_e00 = e0;
        }
    }

    // block reduce max/min over the 400 grid points
    #pragma unroll
    for (int off = 16; off; off >>= 1) {
        lmax = fmaxf(lmax, __shfl_xor_sync(0xffffffffu, lmax, off));
        lmin = fminf(lmin, __shfl_xor_sync(0xffffffffu, lmin, off));
    }
    if ((tid & 31) == 0) { s_wmax[tid >> 5] = lmax; s_wmin[tid >> 5] = lmin; }
    __syncthreads();

    if (tid == 0) {
        float rmax = fmaxf(fmaxf(s_wmax[0], s_wmax[1]), fmaxf(s_wmax[2], s_wmax[3]));
        float rmin = fminf(fminf(s_wmin[0], s_wmin[1]), fminf(s_wmin[2], s_wmin[3]));
        float rng  = rmax - rmin;
        float xnrm = fabsf(__fdividef(s_e00, rng));
        // |0.1^x - 1| = 1 - exp(-ln(10)*x)
        g_scratch[mp] = 1.0f - __expf(-2.30258509299404568f * xnrm);
    }
}

__global__ void finalize_kernel(const float* __restrict__ bly,
                                float* __restrict__ out, int M, int L, int P)
{
    int m = blockIdx.x * blockDim.x + threadIdx.x;
    if (m >= M) return;
    float s = 0.0f;
    const float* sc = g_scratch + m * P;
    for (int p = 0; p < P; ++p) s += sc[p];
    s *= __fdividef(1.0f, (float)P);

    // vertical smoothness regularizer: sum |Lmat_v @ b| / L  (DAMP_VERTICAL = 1)
    const float* bm = bly + m * L;
    float reg = fabsf(bm[0] - bm[1]);
    for (int i = 1; i < L - 1; ++i)
        reg += fabsf(2.0f * bm[i] - bm[i - 1] - bm[i + 1]);
    reg += fabsf(bm[L - 1] - bm[L - 2]);

    out[m] = s + reg * __fdividef(1.0f, (float)L);
}

extern "C" void kernel_launch(void* const* d_in, const int* in_sizes, int n_in,
                              void* d_out, int out_size)
{
    const float* vlist = (const float*)d_in[0];
    const float* tlist = (const float*)d_in[1];
    const float* dly   = (const float*)d_in[2];
    const float* bly   = (const float*)d_in[3];
    const float* Clist = (const float*)d_in[4];

    int M  = out_size;            // 64
    int P  = in_sizes[0] / M;     // 100
    int L  = in_sizes[2] / M;     // 32
    int NC = in_sizes[4];         // 400

    disp_kernel<<<M * P, 128>>>(vlist, tlist, dly, bly, Clist, M, L, P, NC);
    finalize_kernel<<<(M + 63) / 64, 64>>>(bly, (float*)d_out, M, L, P);
}

// round 2
// speedup vs baseline: 1.0530x; 1.0530x over previous
#include <cuda_runtime.h>
#include <cuda_bf16.h>

#define LMAX 32
#define NCMAX 512

// scratch: per-(m,p) partial |0.1^|e00/rng| - 1| values (M*P = 6400 max)
__device__ float g_scratch[64 * 100];

typedef unsigned long long u64;

__device__ __forceinline__ float f_rcp(float x) {
    float r; asm("rcp.approx.f32 %0, %1;" : "=f"(r) : "f"(x)); return r;
}
__device__ __forceinline__ float f_sqrt(float x) {
    float r; asm("sqrt.approx.f32 %0, %1;" : "=f"(r) : "f"(x)); return r;
}

// ---- packed f32x2 helpers (sm_100+/sm_103a) ----
__device__ __forceinline__ u64 pk2(float lo, float hi) {
    u64 r; asm("mov.b64 %0, {%1, %2};" : "=l"(r) : "f"(lo), "f"(hi)); return r;
}
__device__ __forceinline__ u64 bc2(float s) {
    u64 r; asm("mov.b64 %0, {%1, %1};" : "=l"(r) : "f"(s)); return r;
}
__device__ __forceinline__ void up2(u64 v, float& lo, float& hi) {
    asm("mov.b64 {%0, %1}, %2;" : "=f"(lo), "=f"(hi) : "l"(v));
}
__device__ __forceinline__ u64 mul2(u64 a, u64 b) {
    u64 d; asm("mul.rn.f32x2 %0, %1, %2;" : "=l"(d) : "l"(a), "l"(b)); return d;
}
__device__ __forceinline__ u64 add2(u64 a, u64 b) {
    u64 d; asm("add.rn.f32x2 %0, %1, %2;" : "=l"(d) : "l"(a), "l"(b)); return d;
}
__device__ __forceinline__ u64 fma2(u64 a, u64 b, u64 c) {
    u64 d; asm("fma.rn.f32x2 %0, %1, %2, %3;" : "=l"(d) : "l"(a), "l"(b), "l"(c)); return d;
}
// a - b  ==  b * (-1) + a
__device__ __forceinline__ u64 sub2(u64 a, u64 b) {
    const u64 NEG1 = 0xBF800000BF800000ULL;
    return fma2(b, NEG1, a);
}

// one half of _var: scalar (branchy + MUFU-heavy)
__device__ __forceinline__ void var_half(
    float wv, float w2, float k, float k2, float dm,
    float& cosv, float& wo, float& xo, float& exo)
{
    float r  = f_sqrt(fabsf(w2 - k2));
    float pp = r * dm;
    if (wv < k) {
        float s, c; __sincosf(pp, &s, &c);
        float ir = f_rcp((r > 0.0f) ? r : 1.0f);
        cosv = c; wo = s * ir; xo = -r * s; exo = 0.0f;
    } else if (wv > k) {
        float fac = (pp < 16.0f) ? __expf(-2.0f * pp) : 0.0f;
        float ir  = f_rcp((r > 0.0f) ? r : 1.0f);
        cosv = fmaf(0.5f, fac, 0.5f);
        float se = 0.5f - 0.5f * fac;
        wo = se * ir; xo = r * se; exo = pp;
    } else {
        cosv = 1.0f; wo = dm; xo = 0.0f; exo = 0.0f;
    }
}

__global__ void __launch_bounds__(224)
disp_kernel(const float* __restrict__ vlist, const float* __restrict__ tlist,
            const float* __restrict__ dly, const float* __restrict__ bly,
            const float* __restrict__ Clist,
            int M, int L, int P, int NC)
{
    __shared__ float s_xka[LMAX], s_xka2[LMAX], s_xkb[LMAX], s_xkb2[LMAX];
    __shared__ float s_gk[LMAX], s_d[LMAX], s_rho[LMAX], s_irho[LMAX];
    __shared__ float s_C[NCMAX];
    __shared__ float s_wmax[8], s_wmin[8], s_e00;

    const int mp  = blockIdx.x;          // mp = m*P + p
    const int m   = mp / P;
    const int tid = threadIdx.x;

    const float omega = fmaxf(6.28318530717958647692f / tlist[mp], 1.0e-4f);
    const float v     = vlist[mp];
    const float io    = f_rcp(omega);

    // Phase 0: per-(m,p,layer) constants, shared across all wvno points
    for (int l = tid; l < L; l += blockDim.x) {
        float bb = bly[m * L + l];
        float dd = dly[m * L + l];
        float b2 = bb * bb;
        float aa = 0.9409f + 2.0947f * bb - 0.8206f * b2 + 0.2683f * b2 * bb
                 - 0.0251f * b2 * b2;
        float a2 = aa * aa;
        float rho = 1.6612f * aa - 0.4721f * a2 + 0.0671f * a2 * aa
                  - 0.0043f * a2 * a2 + 0.000106f * a2 * a2 * aa;
        float xka = __fdividef(omega, aa);
        float xkb = __fdividef(omega, bb);
        s_xka[l]  = xka;  s_xka2[l] = xka * xka;
        s_xkb[l]  = xkb;  s_xkb2[l] = xkb * xkb;
        float tt  = bb * io;
        s_gk[l]   = 2.0f * tt * tt;
        s_d[l]    = dd;
        s_rho[l]  = rho;
        s_irho[l] = f_rcp(rho);
    }
    for (int i = tid; i < NC; i += blockDim.x) s_C[i] = Clist[i];
    __syncthreads();

    const int npair = NC >> 1;           // 200
    float lmax = -3.4e38f, lmin = 3.4e38f;
    const bool is_v   = (tid == npair);
    const bool active = (tid < npair) || is_v;

    if (active) {
        const float c0 = is_v ? v : s_C[2 * tid];
        const float c1 = is_v ? v : s_C[2 * tid + 1];
        const float wvlo = __fdividef(omega, c0);
        const float wvhi = __fdividef(omega, c1);
        const float w2lo = wvlo * wvlo, w2hi = wvhi * wvhi;
        const u64 wv2p = pk2(w2lo, w2hi);
        const u64 NEG1f = 0xBF800000BF800000ULL;   // {-1,-1}
        const u64 NEG2f = 0xC0000000C0000000ULL;   // {-2,-2}
        const u64 SGN   = 0x8000000080000000ULL;

        // ---- halfspace initial vector (layer L-1), scalar per half ----
        u64 e0, e1, e2, e3, e4;
        {
            const int lh = L - 1;
            const float xka2 = s_xka2[lh], xkb2 = s_xkb2[lh];
            const float gk = s_gk[lh], r = s_rho[lh];
            float e0h[2], e1h[2], e2h[2], e3h[2], e4h[2];
            #pragma unroll
            for (int h = 0; h < 2; ++h) {
                float w2 = h ? w2hi : w2lo;
                float ra = f_sqrt(fabsf(w2 - xka2));
                float rb = f_sqrt(fabsf(w2 - xkb2));
                float gam = gk * w2, gamm1 = gam - 1.0f, rarb = ra * rb;
                e0h[h] = r * r * (gamm1 * gamm1 - gam * gk * rarb);
                e1h[h] = -r * ra;
                e2h[h] = r * (gamm1 - gk * rarb);
                e3h[h] = r * rb;
                e4h[h] = w2 - rarb;
            }
            e0 = pk2(e0h[0], e0h[1]); e1 = pk2(e1h[0], e1h[1]);
            e2 = pk2(e2h[0], e2h[1]); e3 = pk2(e3h[0], e3h[1]);
            e4 = pk2(e4h[0], e4h[1]);
        }

        // ---- layer recursion L-2 .. 0 ----
        #pragma unroll 1
        for (int l = L - 2; l >= 0; --l) {
            const float xka = s_xka[l], xka2 = s_xka2[l];
            const float xkb = s_xkb[l], xkb2 = s_xkb2[l];
            const float gk = s_gk[l], dm = s_d[l];
            const float rho = s_rho[l], irho = s_irho[l];

            // scalar per-half var (MUFU + branches)
            float cplo, wlo, xlo, exp_lo, cphi, whi, xhi, exp_hi;
            float cqlo, ylo, zlo, exq_lo, cqhi, yhi, zhi, exq_hi;
            var_half(wvlo, w2lo, xka, xka2, dm, cplo, wlo, xlo, exp_lo);
            var_half(wvhi, w2hi, xka, xka2, dm, cphi, whi, xhi, exp_hi);
            var_half(wvlo, w2lo, xkb, xkb2, dm, cqlo, ylo, zlo, exq_lo);
            var_half(wvhi, w2hi, xkb, xkb2, dm, cqhi, yhi, zhi, exq_hi);
            float exalo = exp_lo + exq_lo;
            float exahi = exp_hi + exq_hi;
            float a0lo = (exalo < 60.0f) ? __expf(-exalo) : 0.0f;
            float a0hi = (exahi < 60.0f) ? __expf(-exahi) : 0.0f;

            // pack var outputs + layer constants
            const u64 cosp = pk2(cplo, cphi), cosq = pk2(cqlo, cqhi);
            const u64 wp = pk2(wlo, whi), xp = pk2(xlo, xhi);
            const u64 yp = pk2(ylo, yhi), zp = pk2(zlo, zhi);
            const u64 a0p = pk2(a0lo, a0hi);
            const u64 gk2    = bc2(gk);
            const u64 rhob   = bc2(rho);
            const u64 nrhob  = bc2(-rho);
            const u64 nrhoq  = bc2(-rho * rho);
            const u64 irhob  = bc2(irho);
            const u64 nirhob = bc2(-irho);
            const u64 nirho2 = bc2(-irho * irho);

            // packed products
            const u64 cpcq = mul2(cosp, cosq);
            const u64 cpy = mul2(cosp, yp), cpz = mul2(cosp, zp);
            const u64 cqw = mul2(cosq, wp), cqx = mul2(cosq, xp);
            const u64 xy = mul2(xp, yp), xz = mul2(xp, zp);
            const u64 wy = mul2(wp, yp), wz = mul2(wp, zp);

            const u64 gam   = mul2(gk2, wv2p);
            const u64 gamm1 = add2(gam, NEG1f);
            const u64 twgm1 = add2(gam, gamm1);
            const u64 gmgmk = mul2(gam, gk2);
            const u64 gmgm1 = mul2(gam, gamm1);
            const u64 gm1sq = mul2(gamm1, gamm1);
            const u64 a0pq  = sub2(a0p, cpcq);
            const u64 a0pq2 = add2(a0pq, a0pq);
            const u64 wv2wy = mul2(wv2p, wy);

            // c00 = cpcq - gmgm1*a0pq2 - gmgmk*xz - gm1sq*wv2wy
            u64 c00 = sub2(cpcq, mul2(gmgm1, a0pq2));
            c00 = sub2(c00, mul2(gmgmk, xz));
            c00 = sub2(c00, mul2(gm1sq, wv2wy));
            // c01 = (wv2*cpy - cqx) * irho
            const u64 c01 = mul2(sub2(mul2(wv2p, cpy), cqx), irhob);
            // c02 = -(twgm1*a0pq + gk*xz + gamm1*wv2wy) * irho
            u64 t02 = mul2(twgm1, a0pq);
            t02 = fma2(gk2, xz, t02);
            t02 = fma2(gamm1, wv2wy, t02);
            const u64 c02 = mul2(t02, nirhob);
            // c03 = (cpz - wv2*cqw) * irho
            const u64 c03 = mul2(sub2(cpz, mul2(wv2p, cqw)), irhob);
            // c04 = -(wv2*a0pq2 + xz + wv2*wv2wy) * irho^2
            u64 t04 = mul2(wv2p, a0pq2);
            t04 = add2(t04, xz);
            t04 = fma2(wv2p, wv2wy, t04);
            const u64 c04 = mul2(t04, nirho2);
            // c10 = (gmgmk*cpz - gm1sq*cqw) * rho
            const u64 c10 = mul2(sub2(mul2(gmgmk, cpz), mul2(gm1sq, cqw)), rhob);
            // c12 = gk*cpz - gamm1*cqw
            const u64 c12 = sub2(mul2(gk2, cpz), mul2(gamm1, cqw));
            const u64 c13 = wz ^ SGN;      // -wz
            // c30 = (gm1sq*cpy - gmgmk*cqx) * rho
            const u64 c30 = mul2(sub2(mul2(gm1sq, cpy), mul2(gmgmk, cqx)), rhob);
            const u64 c31 = xy ^ SGN;      // -xy
            // c32 = gamm1*cpy - gk*cqx
            const u64 c32 = sub2(mul2(gamm1, cpy), mul2(gk2, cqx));
            // c40 = -(gmgmk*gm1sq*a0pq2 + gmgmk^2*xz + gm1sq^2*wy) * rho^2
            u64 t40 = mul2(mul2(gmgmk, gm1sq), a0pq2);
            t40 = fma2(mul2(gmgmk, gmgmk), xz, t40);
            t40 = fma2(mul2(gm1sq, gm1sq), wy, t40);
            const u64 c40 = mul2(t40, nrhoq);
            // c42 = -(gk*gamm1*twgm1*a0pq + gam*gk*gk*xz + gamm1*gm1sq*wy) * rho
            u64 t42 = mul2(mul2(mul2(gk2, gamm1), twgm1), a0pq);
            t42 = fma2(mul2(gmgmk, gk2), xz, t42);
            t42 = fma2(mul2(gamm1, gm1sq), wy, t42);
            const u64 c42 = mul2(t42, nrhob);

            const u64 tneg = mul2(wv2p, NEG2f);
            const u64 c20 = mul2(tneg, c42);
            const u64 c21 = mul2(tneg, c32);
            const u64 c23 = mul2(tneg, c12);
            const u64 c24 = mul2(tneg, c02);
            const u64 dd  = sub2(cpcq, c00);
            const u64 c22 = add2(a0p, add2(dd, dd));

            // matvec: n_i = sum_j e_j * ca[j][i]
            u64 n0 = mul2(e0, c00);
            n0 = fma2(e1, c10, n0); n0 = fma2(e2, c20, n0);
            n0 = fma2(e3, c30, n0); n0 = fma2(e4, c40, n0);
            u64 n1 = mul2(e0, c01);
            n1 = fma2(e1, cpcq, n1); n1 = fma2(e2, c21, n1);
            n1 = fma2(e3, c31, n1);  n1 = fma2(e4, c30, n1);
            u64 n2 = mul2(e0, c02);
            n2 = fma2(e1, c12, n2); n2 = fma2(e2, c22, n2);
            n2 = fma2(e3, c32, n2); n2 = fma2(e4, c42, n2);
            u64 n3 = mul2(e0, c03);
            n3 = fma2(e1, c13, n3); n3 = fma2(e2, c23, n3);
            n3 = fma2(e3, cpcq, n3); n3 = fma2(e4, c10, n3);
            u64 n4 = mul2(e0, c04);
            n4 = fma2(e1, c03, n4); n4 = fma2(e2, c24, n4);
            n4 = fma2(e3, c01, n4); n4 = fma2(e4, c00, n4);

            // per-half renormalization
            float alo, ahi, blo, bhi, clo, chi, dlo, dhi, elo, ehi;
            up2(n0, alo, ahi); up2(n1, blo, bhi); up2(n2, clo, chi);
            up2(n3, dlo, dhi); up2(n4, elo, ehi);
            float tlo = fmaxf(fmaxf(fabsf(alo), fabsf(blo)),
                              fmaxf(fmaxf(fabsf(clo), fabsf(dlo)), fabsf(elo)));
            float thi = fmaxf(fmaxf(fabsf(ahi), fabsf(bhi)),
                              fmaxf(fmaxf(fabsf(chi), fabsf(dhi)), fabsf(ehi)));
            tlo = (tlo < 1e-30f) ? 1.0f : tlo;
            thi = (thi < 1e-30f) ? 1.0f : thi;
            const u64 it = pk2(f_rcp(tlo), f_rcp(thi));
            e0 = mul2(n0, it); e1 = mul2(n1, it); e2 = mul2(n2, it);
            e3 = mul2(n3, it); e4 = mul2(n4, it);
        }

        float r0, r1; up2(e0, r0, r1);
        if (is_v) {
            s_e00 = r0;
        } else {
            lmax = fmaxf(lmax, fmaxf(r0, r1));
            lmin = fminf(lmin, fminf(r0, r1));
        }
    }

    // block reduce max/min over the grid points (all threads participate)
    #pragma unroll
    for (int off = 16; off; off >>= 1) {
        lmax = fmaxf(lmax, __shfl_xor_sync(0xffffffffu, lmax, off));
        lmin = fminf(lmin, __shfl_xor_sync(0xffffffffu, lmin, off));
    }
    if ((tid & 31) == 0) { s_wmax[tid >> 5] = lmax; s_wmin[tid >> 5] = lmin; }
    __syncthreads();

    if (tid == 0) {
        const int nw = (int)(blockDim.x >> 5);
        float rmax = s_wmax[0], rmin = s_wmin[0];
        for (int wq = 1; wq < nw; ++wq) {
            rmax = fmaxf(rmax, s_wmax[wq]);
            rmin = fminf(rmin, s_wmin[wq]);
        }
        float rng  = rmax - rmin;
        float xnrm = fabsf(__fdividef(s_e00, rng));
        // |0.1^x - 1| = 1 - exp(-ln(10)*x)
        g_scratch[mp] = 1.0f - __expf(-2.30258509299404568f * xnrm);
    }
}

__global__ void finalize_kernel(const float* __restrict__ bly,
                                float* __restrict__ out, int M, int L, int P)
{
    const int m = blockIdx.x;
    const int lane = threadIdx.x;
    float s = 0.0f;
    for (int p = lane; p < P; p += 32) s += g_scratch[m * P + p];
    #pragma unroll
    for (int off = 16; off; off >>= 1) s += __shfl_xor_sync(0xffffffffu, s, off);

    if (lane == 0) {
        const float* bm = bly + m * L;
        float reg = fabsf(bm[0] - bm[1]);
        for (int i = 1; i < L - 1; ++i)
            reg += fabsf(2.0f * bm[i] - bm[i - 1] - bm[i + 1]);
        reg += fabsf(bm[L - 1] - bm[L - 2]);
        out[m] = s * __fdividef(1.0f, (float)P) + reg * __fdividef(1.0f, (float)L);
    }
}

extern "C" void kernel_launch(void* const* d_in, const int* in_sizes, int n_in,
                              void* d_out, int out_size)
{
    const float* vlist = (const float*)d_in[0];
    const float* tlist = (const float*)d_in[1];
    const float* dly   = (const float*)d_in[2];
    const float* bly   = (const float*)d_in[3];
    const float* Clist = (const float*)d_in[4];

    int M  = out_size;            // 64
    int P  = in_sizes[0] / M;     // 100
    int L  = in_sizes[2] / M;     // 32
    int NC = in_sizes[4];         // 400

    int threads = (((NC >> 1) + 1 + 31) / 32) * 32;   // 224 for NC=400
    disp_kernel<<<M * P, threads>>>(vlist, tlist, dly, bly, Clist, M, L, P, NC);
    finalize_kernel<<<M, 32>>>(bly, (float*)d_out, M, L, P);
}